// round 13
// baseline (speedup 1.0000x reference)
#include <cuda_runtime.h>
#include <stdint.h>

#define NB 256
#define LL 1024
#define TT 128
#define THREADS 128
#define TSTRIDE 129
#define FULL 0xffffffffu
#define NEGINF __int_as_float(0xff800000)

// smem layout (bytes), all 16B-aligned
#define OFF_TRANST 0          // 128*129*4 = 66048
#define OFF_BP     66048      // 131072 -> 197120
#define OFF_TAGS   197120     // 4096   -> 201216
#define OFF_STATE  201216     // 2*128*4 = 1024 -> 202240
#define OFF_WMAX   202240     // 2*4*4 = 32 -> 202272
#define OFF_OVF    202272     // 2*4*4 = 32 -> 202304
#define OFF_SEG    202304     // 2*4*4*8 = 256 -> 202560
#define OFF_RED    202560     // 1024 -> 203584
#define SMEM_BYTES 203584

__device__ int d_sched[NB];

// order-preserving float <-> uint map
__device__ __forceinline__ unsigned fmap(float f) {
    unsigned u = __float_as_uint(f);
    return (u & 0x80000000u) ? ~u : (u | 0x80000000u);
}
__device__ __forceinline__ float funmap(unsigned u) {
    return __uint_as_float((u & 0x80000000u) ? (u ^ 0x80000000u) : ~u);
}

// first-argmax pairwise combine: better value, or equal value with smaller index.
// associative + commutative -> order-independent.
__device__ __forceinline__ void pairmax(float &va, int &ia, float vb, int ib) {
    bool better = (vb > va) || ((vb == va) && (ib < ia));
    va = better ? vb : va;
    ia = better ? ib : ia;
}

// ---- pre-kernel: LPT schedule (bitonic sort, descending by length) ----
__global__ void sched_kernel(const int* __restrict__ lengths)
{
    __shared__ unsigned key[NB];
    int i = threadIdx.x;
    unsigned l = (unsigned)max(0, min(LL, lengths[i]));
    key[i] = (l << 8) | (255u - (unsigned)i);
    __syncthreads();
    for (int k = 2; k <= NB; k <<= 1) {
        for (int j = k >> 1; j > 0; j >>= 1) {
            int ixj = i ^ j;
            if (ixj > i) {
                unsigned a = key[i], b2 = key[ixj];
                bool up = ((i & k) == 0);
                bool sw = up ? (a < b2) : (a > b2);
                if (sw) { key[i] = b2; key[ixj] = a; }
            }
            __syncthreads();
        }
    }
    d_sched[i] = 255 - (int)(key[i] & 0xFFu);
}

__global__ __launch_bounds__(THREADS, 1)
void crf_decode_kernel(const float* __restrict__ x,
                       const int* __restrict__ lengths,
                       const float* __restrict__ trans,
                       float* __restrict__ out)
{
    extern __shared__ char smem[];
    float*    s_transT = (float*)(smem + OFF_TRANST);   // [j][i] stride 129
    uint8_t*  s_bp     = (uint8_t*)(smem + OFF_BP);
    int*      s_tags   = (int*)(smem + OFF_TAGS);
    float*    s_state  = (float*)(smem + OFF_STATE);    // [2][128]
    unsigned* s_wmax   = (unsigned*)(smem + OFF_WMAX);  // [2][4]
    int*      s_ovf    = (int*)(smem + OFF_OVF);        // [2][4]
    int2*     s_seg    = (int2*)(smem + OFF_SEG);       // [2][4][4]
    float*    s_red    = (float*)(smem + OFF_RED);

    const int tid  = threadIdx.x;
    const int lane = tid & 31;
    const int w    = tid >> 5;
    const int b    = d_sched[blockIdx.x];

    int len = lengths[b];
    if (len > LL) len = LL;
    if (len < 1)  len = 1;

    // ---- transposed trans load + min/max fold ----
    {
        float mx = -3.4e38f, mn = 3.4e38f;
        #pragma unroll 4
        for (int i = 0; i < TT; ++i) {
            float v = trans[i * TT + tid];
            s_transT[tid * TSTRIDE + i] = v;
            mx = fmaxf(mx, v);
            mn = fminf(mn, v);
        }
        s_red[tid]       = mx;
        s_red[128 + tid] = mn;
    }
    __syncthreads();

    float D;
    {
        float gmx = -3.4e38f, gmn = 3.4e38f;
        const float4* r4 = (const float4*)s_red;
        #pragma unroll 8
        for (int k = 0; k < 32; ++k) {
            float4 a = r4[k];
            gmx = fmaxf(gmx, fmaxf(fmaxf(a.x, a.y), fmaxf(a.z, a.w)));
            float4 c = r4[32 + k];
            gmn = fminf(gmn, fminf(fminf(c.x, c.y), fminf(c.z, c.w)));
        }
        D = (gmx - gmn) * 1.001f + 0.01f;               // exact-pruning width + margin
        if (!(D >= 0.01f && D <= 1000.0f)) D = 3.0e38f; // anomaly -> dense every step
    }

    const float* xb = x + (size_t)b * (LL * TT);
    float sj = xb[tid];

    float xA = (len > 1) ? xb[(size_t)1 * TT + tid] : 0.0f;
    float xB = (len > 2) ? xb[(size_t)2 * TT + tid] : 0.0f;
    float xC = (len > 3) ? xb[(size_t)3 * TT + tid] : 0.0f;

    const float* rowT = s_transT + tid * TSTRIDE;
    const unsigned below = (1u << lane) - 1u;

    // publish current sj into parity buffer BUF: fixed 4 slots/warp + sentinels.
    #define PUBLISH(BUF)                                                         \
    {                                                                            \
        unsigned wmu = __reduce_max_sync(FULL, fmap(sj));                        \
        float wmf = funmap(wmu);                                                 \
        bool pred = (sj >= wmf - D);                                             \
        unsigned bal = __ballot_sync(FULL, pred);                                \
        int cnt = __popc(bal);                                                   \
        int pos = __popc(bal & below);                                           \
        int2* sg = s_seg + ((BUF) << 4) + (w << 2);                              \
        if (pred && pos < 4) sg[pos] = make_int2(__float_as_int(sj), tid);       \
        if (lane < 4 && lane >= cnt) sg[lane] = make_int2((int)0xff800000, 0);   \
        s_state[((BUF) << 7) + tid] = sj;                                        \
        if (lane == 0) {                                                         \
            s_wmax[((BUF) << 2) + w] = wmu;                                      \
            s_ovf [((BUF) << 2) + w] = (cnt > 4);                                \
        }                                                                        \
    }

    PUBLISH(0)

    for (int t = 1; t < len; ++t) {
        __syncthreads();                                // single barrier per step
        const int p  = (t - 1) & 1;
        const int np = t & 1;

        const uint4 wm = *(const uint4*)(s_wmax + (p << 2));
        const int4  ov = *(const int4*)(s_ovf  + (p << 2));
        float thr = funmap(max(max(wm.x, wm.y), max(wm.z, wm.w))) - D;

        float xcur = xA; xA = xB; xB = xC;
        xC = (t + 3 < len) ? xb[(size_t)(t + 3) * TT + tid] : 0.0f;

        float best; int bi;
        if ((ov.x | ov.y | ov.z | ov.w) == 0) {
            // ---- fast path: 16 fixed entries, fully unrolled, tree reduce ----
            const int4* sg4 = (const int4*)(s_seg + (p << 4));  // 8 x int4 = 16 entries
            int4 e0 = sg4[0], e1 = sg4[1], e2 = sg4[2], e3 = sg4[3];
            int4 e4 = sg4[4], e5 = sg4[5], e6 = sg4[6], e7 = sg4[7];

            float v[16]; int id[16];
            #define ENT(slot, sv_bits, idx_)                                     \
            { float sv = __int_as_float(sv_bits); int ii = (idx_);               \
              v[slot]  = (sv >= thr) ? (sv + rowT[ii]) : NEGINF;                 \
              id[slot] = ii; }
            ENT(0,  e0.x, e0.y) ENT(1,  e0.z, e0.w)
            ENT(2,  e1.x, e1.y) ENT(3,  e1.z, e1.w)
            ENT(4,  e2.x, e2.y) ENT(5,  e2.z, e2.w)
            ENT(6,  e3.x, e3.y) ENT(7,  e3.z, e3.w)
            ENT(8,  e4.x, e4.y) ENT(9,  e4.z, e4.w)
            ENT(10, e5.x, e5.y) ENT(11, e5.z, e5.w)
            ENT(12, e6.x, e6.y) ENT(13, e6.z, e6.w)
            ENT(14, e7.x, e7.y) ENT(15, e7.z, e7.w)
            #undef ENT

            // depth-4 pairmax tree (order-independent first-argmax)
            #pragma unroll
            for (int s = 1; s < 16; s <<= 1)
                #pragma unroll
                for (int k = 0; k < 16; k += (s << 1))
                    pairmax(v[k], id[k], v[k + s], id[k + s]);
            best = v[0]; bi = id[0];
        } else {
            // ---- exact dense fallback (rare) ----
            const float* st = s_state + (p << 7);
            best = NEGINF; bi = 0;
            #pragma unroll 4
            for (int i = 0; i < TT; ++i) {
                float vv = st[i] + rowT[i];
                if ((vv > best) || ((vv == best) && (i < bi))) { best = vv; bi = i; }
            }
        }

        s_bp[(t << 7) + tid] = (uint8_t)bi;
        sj = best + xcur;                               // reference op order

        PUBLISH(np)
    }
    #undef PUBLISH

    // ---- final argmax (first-max) + backward walk ----
    __syncthreads();
    s_red[tid] = sj;
    __syncthreads();
    if (tid == 0) {
        float bestf = s_red[0];
        int cand = 0;
        for (int i = 1; i < TT; ++i) {
            float v2 = s_red[i];
            if (v2 > bestf) { bestf = v2; cand = i; }
        }
        int carry = cand;
        for (int t = len - 1; t >= 1; --t) {
            s_tags[t] = carry;
            carry = (int)s_bp[(t << 7) + carry];
        }
        s_tags[0] = carry;
    }
    __syncthreads();

    // ---- output: float32 tags for t < len, zeros beyond ----
    float* orow = out + b * LL;
    #pragma unroll 2
    for (int k = tid; k < LL / 4; k += THREADS) {
        int base = k << 2;
        float4 v;
        v.x = (base + 0 < len) ? (float)s_tags[base + 0] : 0.0f;
        v.y = (base + 1 < len) ? (float)s_tags[base + 1] : 0.0f;
        v.z = (base + 2 < len) ? (float)s_tags[base + 2] : 0.0f;
        v.w = (base + 3 < len) ? (float)s_tags[base + 3] : 0.0f;
        ((float4*)orow)[k] = v;
    }
}

extern "C" void kernel_launch(void* const* d_in, const int* in_sizes, int n_in,
                              void* d_out, int out_size)
{
    const float* x       = nullptr;
    const int*   lengths = nullptr;
    const float* trans   = nullptr;
    for (int i = 0; i < n_in; ++i) {
        long s = in_sizes[i];
        if      (s == 33554432L || s == 134217728L) x       = (const float*)d_in[i];
        else if (s == 256L      || s == 1024L)      lengths = (const int*)d_in[i];
        else if (s == 16384L    || s == 65536L)     trans   = (const float*)d_in[i];
    }
    if (!x       && n_in > 0) x       = (const float*)d_in[0];
    if (!lengths && n_in > 1) lengths = (const int*)d_in[1];
    if (!trans   && n_in > 3) trans   = (const float*)d_in[3];

    sched_kernel<<<1, NB>>>(lengths);

    cudaFuncSetAttribute(crf_decode_kernel,
                         cudaFuncAttributeMaxDynamicSharedMemorySize, SMEM_BYTES);
    crf_decode_kernel<<<NB, THREADS, SMEM_BYTES>>>(x, lengths, trans, (float*)d_out);
}

// round 14
// speedup vs baseline: 2.4308x; 2.4308x over previous
#include <cuda_runtime.h>
#include <stdint.h>

#define NB 256
#define LL 1024
#define TT 128
#define TSTRIDE 129          // padded row stride (floats) -> conflict-free smem rows
#define THREADS 128
#define FULL 0xffffffffu

// dynamic smem layout (bytes) -- identical to the 506us round-4 kernel
#define OFF_TRANST 0                                   // 128*129*4 = 66048
#define OFF_BP     (TT * TSTRIDE * 4)                  // 66048, size 1024*128 = 131072
#define OFF_TAGS   (OFF_BP + LL * TT)                  // 197120, size 4096
#define OFF_RED    (OFF_TAGS + LL * 4)                 // 201216, size 2048
#define SMEM_BYTES (OFF_RED + 2048)                    // 203264

__device__ int d_sched[NB];

// order-preserving float -> uint map (for __reduce_max_sync)
__device__ __forceinline__ unsigned fmap(float f) {
    unsigned u = __float_as_uint(f);
    return (u & 0x80000000u) ? ~u : (u | 0x80000000u);
}
__device__ __forceinline__ float funmap(unsigned u) {
    return __uint_as_float((u & 0x80000000u) ? (u ^ 0x80000000u) : ~u);
}

// ---- pre-kernel: LPT schedule (bitonic sort of 256 keys, descending by length) ----
__global__ void sched_kernel(const int* __restrict__ lengths)
{
    __shared__ unsigned key[NB];
    int i = threadIdx.x;
    unsigned l = (unsigned)max(0, min(LL, lengths[i]));
    key[i] = (l << 8) | (255u - (unsigned)i);      // desc len, asc idx on ties
    __syncthreads();
    for (int k = 2; k <= NB; k <<= 1) {
        for (int j = k >> 1; j > 0; j >>= 1) {
            int ixj = i ^ j;
            if (ixj > i) {
                unsigned a = key[i], b2 = key[ixj];
                bool up = ((i & k) == 0);
                bool sw = up ? (a < b2) : (a > b2);
                if (sw) { key[i] = b2; key[ixj] = a; }
            }
            __syncthreads();
        }
    }
    d_sched[i] = 255 - (int)(key[i] & 0xFFu);
}

__global__ __launch_bounds__(THREADS, 1)
void crf_decode_kernel(const float* __restrict__ x,
                       const int* __restrict__ lengths,
                       const float* __restrict__ trans,
                       float* __restrict__ out)          // float32 output (validated)
{
    extern __shared__ char smem[];
    float*    s_transT = (float*)(smem + OFF_TRANST);          // [j][i], stride 129
    uint8_t*  s_bp     = (uint8_t*)(smem + OFF_BP);            // [t][j]
    int*      s_tags   = (int*)(smem + OFF_TAGS);
    float*    s_red    = (float*)(smem + OFF_RED);             // [0..127] mx, [128..255] mn
    float*    s_D      = s_red + 256;
    float*    s_state  = s_red + 260;                          // 128 floats
    unsigned* s_wmax   = (unsigned*)(s_state + TT);            // 4
    unsigned* s_mask   = s_wmax + 4;                           // 4

    const int tid  = threadIdx.x;
    const int lane = tid & 31;
    const int w    = tid >> 5;
    const int b    = d_sched[blockIdx.x];                      // ONLY change vs round 4

    int len = lengths[b];
    if (len > LL) len = LL;

    // ---- transpose trans into smem; fold per-thread min/max (thread owns column tid) ----
    {
        float mx = -3.4e38f, mn = 3.4e38f;
        #pragma unroll 4
        for (int i = 0; i < TT; ++i) {
            float v = trans[i * TT + tid];         // coalesced per i
            s_transT[tid * TSTRIDE + i] = v;       // conflict-free (stride 129)
            mx = fmaxf(mx, v);
            mn = fminf(mn, v);
        }
        s_red[tid]       = mx;
        s_red[128 + tid] = mn;
    }

    const float* xb = x + (size_t)b * (LL * TT);
    float sj = xb[tid];                            // state_0[j] = x[b,0,j]
    s_state[tid] = sj;
    __syncthreads();

    if (tid == 0) {
        float gmx = -3.4e38f, gmn = 3.4e38f;
        for (int k = 0; k < TT; ++k) {
            gmx = fmaxf(gmx, s_red[k]);
            gmn = fminf(gmn, s_red[128 + k]);
        }
        float D = (gmx - gmn) * 1.001f + 0.01f;    // exact pruning width + fp margin
        if (!(D >= 0.01f && D <= 1000.0f)) D = 3.0e38f;   // dense fallback
        *s_D = D;
    }
    __syncthreads();
    const float D = *s_D;
    const float* rowT = s_transT + tid * TSTRIDE;

    float xt = (len > 1) ? xb[TT + tid] : 0.0f;    // prefetched x row t=1

    for (int t = 1; t < len; ++t) {
        // block max of state: warp redux on mapped uints, combine via smem
        unsigned wmu = __reduce_max_sync(FULL, fmap(sj));
        if (lane == 0) s_wmax[w] = wmu;
        __syncthreads();                            // BAR1 (also publishes prev state writes)
        unsigned lmu = max(max(s_wmax[0], s_wmax[1]), max(s_wmax[2], s_wmax[3]));
        float thr = funmap(lmu) - D;

        unsigned bal = __ballot_sync(FULL, sj >= thr);
        if (lane == 0) s_mask[w] = bal;
        __syncthreads();                            // BAR2

        unsigned m0 = s_mask[0], m1 = s_mask[1], m2 = s_mask[2], m3 = s_mask[3];
        if ((m0 | m1 | m2 | m3) == 0u) {            // impossible with sane D; dense fallback
            m0 = m1 = m2 = m3 = 0xffffffffu;
        }

        float xn = (t + 1 < len) ? xb[(size_t)(t + 1) * TT + tid] : 0.0f;

        // survivor scan, ascending i -> strict '>' keeps first argmax (reference semantics)
        float best = -3.4e38f;
        int   bi   = 0;
        #pragma unroll
        for (int w2 = 0; w2 < 4; ++w2) {
            unsigned mm = (w2 == 0) ? m0 : (w2 == 1) ? m1 : (w2 == 2) ? m2 : m3;
            while (mm) {
                int l2 = __ffs(mm) - 1; mm &= mm - 1;
                int i  = (w2 << 5) + l2;
                float v = s_state[i] + rowT[i];     // broadcast LDS + conflict-free LDS
                if (v > best) { best = v; bi = i; }
            }
        }

        s_bp[t * TT + tid] = (uint8_t)bi;
        float newsj = best + xt;                    // max + x_t (reference order)
        xt = xn;
        __syncthreads();                            // BAR3: all reads of old state done
        sj = newsj;
        s_state[tid] = sj;
    }
    __syncthreads();                                // publish final state

    // ---- final argmax (first-max) + backward walk: thread 0 ----
    if (tid == 0) {
        float bestf = s_state[0];
        int cand = 0;
        for (int i = 1; i < TT; ++i) {
            float v = s_state[i];
            if (v > bestf) { bestf = v; cand = i; }
        }
        int carry = cand;
        for (int t = len - 1; t >= 1; --t) {
            s_tags[t] = carry;
            carry = (int)s_bp[t * TT + carry];
        }
        s_tags[0] = carry;
    }
    __syncthreads();

    // ---- output: float32 tags for t < len, zeros beyond ----
    float* orow = out + b * LL;
    #pragma unroll 4
    for (int k = tid; k < LL / 4; k += THREADS) {
        int base = k << 2;
        float4 v;
        v.x = (base + 0 < len) ? (float)s_tags[base + 0] : 0.0f;
        v.y = (base + 1 < len) ? (float)s_tags[base + 1] : 0.0f;
        v.z = (base + 2 < len) ? (float)s_tags[base + 2] : 0.0f;
        v.w = (base + 3 < len) ? (float)s_tags[base + 3] : 0.0f;
        ((float4*)orow)[k] = v;
    }
}

extern "C" void kernel_launch(void* const* d_in, const int* in_sizes, int n_in,
                              void* d_out, int out_size)
{
    // Size-based identification (element counts or byte counts); positional fallback.
    const float* x       = nullptr;
    const int*   lengths = nullptr;
    const float* trans   = nullptr;
    for (int i = 0; i < n_in; ++i) {
        long s = in_sizes[i];
        if      (s == 33554432L || s == 134217728L) x       = (const float*)d_in[i];
        else if (s == 256L      || s == 1024L)      lengths = (const int*)d_in[i];
        else if (s == 16384L    || s == 65536L)     trans   = (const float*)d_in[i];
        // 262144 / 1048576 = tags (unused)
    }
    if (!x       && n_in > 0) x       = (const float*)d_in[0];
    if (!lengths && n_in > 1) lengths = (const int*)d_in[1];
    if (!trans   && n_in > 3) trans   = (const float*)d_in[3];

    sched_kernel<<<1, NB>>>(lengths);

    cudaFuncSetAttribute(crf_decode_kernel,
                         cudaFuncAttributeMaxDynamicSharedMemorySize, SMEM_BYTES);
    crf_decode_kernel<<<NB, THREADS, SMEM_BYTES>>>(x, lengths, trans, (float*)d_out);
}